// round 16
// baseline (speedup 1.0000x reference)
#include <cuda_runtime.h>
#include <cuda_bf16.h>
#include <cstdint>

typedef __nv_bfloat16 bf;

#define NB_   4
#define BATCH 8
#define LEN   4096
#define FREQ  80
#define DIM   512
#define HID   2048
#define USEQ  1024
#define C1    128
#define C2    256
#define C3    512
#define H1    2048
#define W1    40
#define H2    1024
#define W2    20
#define MCONV (BATCH*H2*W2)      /* 163840 */
#define K2C   (9*C1)             /* 1152 */
#define K3C   (9*C2)             /* 2304 */
#define KE    (C3*W2)            /* 10240 */
#define MT    (BATCH*USEQ)       /* 8192 */
#define HTOK  (MT*DIM)           /* 4194304 */

// ---------------- scratch (device globals; no allocations) ----------------
__device__ bf g_c1h[BATCH*H1*W1*C1], g_c1l[BATCH*H1*W1*C1];
__device__ bf g_c2h[MCONV*C2],     g_c2l[MCONV*C2];
__device__ bf g_c3h[MCONV*C3],     g_c3l[MCONV*C3];
__device__ bf g_yrh[MT*KE],        g_yrl[MT*KE];
__device__ float g_t0[HTOK];
__device__ float g_h[HTOK];
__device__ float g_xn[HTOK];
__device__ bf g_xkh[HTOK], g_xkl[HTOK];
__device__ bf g_xvh[HTOK], g_xvl[HTOK];
__device__ bf g_xrh[HTOK], g_xrl[HTOK];
__device__ float g_k[HTOK];
__device__ float g_v[HTOK];
__device__ float g_r[HTOK];
__device__ bf g_rwh[HTOK], g_rwl[HTOK];
__device__ bf g_kkh[MT*HID], g_kkl[MT*HID];
// transposed+split weights, [N][K] K-major bf16 hi/lo
__device__ bf g_w2Th[C2*K2C],  g_w2Tl[C2*K2C];
__device__ bf g_w3Th[C3*K3C],  g_w3Tl[C3*K3C];
__device__ bf g_ewTh[DIM*KE],  g_ewTl[DIM*KE];
__device__ bf g_aqkvTh[NB_*3*DIM*DIM], g_aqkvTl[NB_*3*DIM*DIM];
__device__ bf g_awoTh[NB_*DIM*DIM],    g_awoTl[NB_*DIM*DIM];
__device__ bf g_fkrTh[NB_*(HID+DIM)*DIM], g_fkrTl[NB_*(HID+DIM)*DIM];
__device__ bf g_fwvTh[NB_*DIM*HID],    g_fwvTl[NB_*DIM*HID];

// ================== helpers ==================
__device__ __forceinline__ uint32_t smem_to_u32(const void* p) {
  uint32_t a;
  asm("{ .reg .u64 t; cvta.to.shared.u64 t, %1; cvt.u32.u64 %0, t; }"
      : "=r"(a) : "l"(p));
  return a;
}
__device__ __forceinline__ void ldsm4(uint32_t* r, uint32_t addr){
  asm volatile("ldmatrix.sync.aligned.m8n8.x4.shared.b16 {%0,%1,%2,%3}, [%4];"
    : "=r"(r[0]),"=r"(r[1]),"=r"(r[2]),"=r"(r[3]) : "r"(addr));
}
__device__ __forceinline__ void mma_bf16(float* d, const uint32_t* a, const uint32_t* b){
  asm volatile("mma.sync.aligned.m16n8k16.row.col.f32.bf16.bf16.f32 "
    "{%0,%1,%2,%3}, {%4,%5,%6,%7}, {%8,%9}, {%0,%1,%2,%3};"
    : "+f"(d[0]),"+f"(d[1]),"+f"(d[2]),"+f"(d[3])
    : "r"(a[0]),"r"(a[1]),"r"(a[2]),"r"(a[3]), "r"(b[0]),"r"(b[1]));
}
__device__ __forceinline__ void cp16(uint32_t s, const void* g){
  asm volatile("cp.async.cg.shared.global [%0], [%1], 16;" :: "r"(s), "l"(g));
}
__device__ __forceinline__ void cp16z(uint32_t s, const void* g, uint32_t sz){
  asm volatile("cp.async.cg.shared.global [%0], [%1], 16, %2;" :: "r"(s), "l"(g), "r"(sz));
}
#define CP_COMMIT() asm volatile("cp.async.commit_group;" ::: "memory")
#define CP_WAIT1()  asm volatile("cp.async.wait_group 1;" ::: "memory")

__device__ __forceinline__ void split2(float v0, float v1, uint32_t& h, uint32_t& l){
  __nv_bfloat162 hh = __floats2bfloat162_rn(v0, v1);
  float r0 = v0 - __bfloat162float(hh.x);
  float r1 = v1 - __bfloat162float(hh.y);
  __nv_bfloat162 ll = __floats2bfloat162_rn(r0, r1);
  h = *(uint32_t*)&hh; l = *(uint32_t*)&ll;
}
__device__ __forceinline__ float sgm(float v){ return 1.f/(1.f + __expf(-v)); }

// ---------------- GEMM pointer bundle (macro-safe names) ------------------------
struct GP {
  const bf* Ah;  const bf* Al;
  const bf* A2h; const bf* A2l;
  const bf* A3h; const bf* A3l;
  const bf* Bh;  const bf* Bl;
  const float* bias;
  float* Co; float* Cv; float* Cr;
  bf* Ch; bf* Cl;
  const float* mul;
};
static inline GP gp0(){
  GP g; g.Ah=nullptr; g.Al=nullptr; g.A2h=nullptr; g.A2l=nullptr;
  g.A3h=nullptr; g.A3l=nullptr; g.Bh=nullptr; g.Bl=nullptr; g.bias=nullptr;
  g.Co=nullptr; g.Cv=nullptr; g.Cr=nullptr; g.Ch=nullptr; g.Cl=nullptr; g.mul=nullptr;
  return g;
}

// ====== bf16x3 MMA GEMM: CTA 128x256, Kchunk=32, 8 warps (64x64 tiles) =======
// ACT: 0 none,1 relu,2 sigmoid,3 relu^2 ; EPI: 0 store,1 +=,2 Co+mul*acc
// OUT: 0 fp32 Co ; 1 bf16 split Ch/Cl
//      2 fused QKV (N=3*DIM, A per n-seg Ah/A2h/A3h; k->Co, v->Cv, r->sig->Cr)
//      3 fused FFN (N=HID+DIM; n<HID: A=Ah relu^2->Ch/Cl stride HID; else A=A3h sig->Cr)
// IMC: 0 dense A ; 1 implicit im2col from c1 (3x3 s2) ; 2 from c2 (3x3 s1)
#define PITCH 40
#define AHI_O 0
#define ALO_O 10240
#define BHI_O 20480
#define BLO_O 40960
#define STG_B 61440
#define MSMEM (3*STG_B)

template<int ACT, int EPI, int OUT, int IMC>
__global__ void __launch_bounds__(256, 1) mgemm_k(int M, int N, int K, GP g){
  extern __shared__ char smarr[];
  uint32_t smb = smem_to_u32(smarr);
  int tid = threadIdx.x, lane = tid & 31, wid = tid >> 5;
  int wm = wid >> 2, wn = wid & 3;          // warp grid 2(m) x 4(n), tiles 64x64
  long m0 = (long)blockIdx.y * 128;
  int  n0 = blockIdx.x * 256;

  const bf* Ause_h = g.Ah; const bf* Ause_l = g.Al;
  if(OUT == 2){
    int seg = n0 >> 9;
    if(seg == 1){ Ause_h = g.A2h; Ause_l = g.A2l; }
    else if(seg == 2){ Ause_h = g.A3h; Ause_l = g.A3l; }
  } else if(OUT == 3){
    if(n0 >= HID){ Ause_h = g.A3h; Ause_l = g.A3l; }
  }

  const bf* Ahb = Ause_h + m0*(long)K;
  const bf* Alb = Ause_l + m0*(long)K;
  const bf* Bhb = g.Bh + (long)n0*K;
  const bf* Blb = g.Bl + (long)n0*K;
  int wseg = tid & 3;
  long lg = (long)(tid >> 2)*K + wseg*8;
  uint32_t ls = (uint32_t)(tid >> 2)*80 + wseg*16;
  long K64 = (long)K*64;

  // implicit im2col per-row decode (output spatial = H2 x W2 for both convs)
  int b0_=0, ho0_=0, wo0_=0, b1_=0, ho1_=0, wo1_=0;
  if(IMC != 0){
    long mA0 = m0 + (tid >> 2);
    long mA1 = mA0 + 64;
    wo0_ = (int)(mA0 % W2); ho0_ = (int)((mA0 / W2) % H2); b0_ = (int)(mA0 / (W2*H2));
    wo1_ = (int)(mA1 % W2); ho1_ = (int)((mA1 / W2) % H2); b1_ = (int)(mA1 / (W2*H2));
  }

  uint32_t aoff = (((uint32_t)wm*64 + ((lane>>3)&1)*8 + (lane&7))*PITCH + ((lane>>4)&1)*8) * 2;
  uint32_t boff = (((uint32_t)wn*64 + ((lane>>4)&1)*8 + (lane&7))*PITCH + ((lane>>3)&1)*8) * 2;

  float acc[4][8][4];
  #pragma unroll
  for(int i=0;i<4;i++)
    #pragma unroll
    for(int j=0;j<8;j++)
      #pragma unroll
      for(int q=0;q<4;q++) acc[i][j][q] = 0.f;

  int nc = K >> 5;

  #define LOAD_A_DENSE(c, stg_) do { \
    long go_ = lg + (long)(c)*32; \
    cp16(stg_ + AHI_O + ls,         Ahb + go_); \
    cp16(stg_ + AHI_O + ls + 5120,  Ahb + go_ + K64); \
    cp16(stg_ + ALO_O + ls,         Alb + go_); \
    cp16(stg_ + ALO_O + ls + 5120,  Alb + go_ + K64); \
  } while(0)

  #define LOAD_A_IMC(c, stg_) do { \
    int r_, cib_; \
    if(IMC == 1){ r_ = (c) >> 2; cib_ = ((c) & 3) << 5; } \
    else        { r_ = (c) >> 3; cib_ = ((c) & 7) << 5; } \
    int kh_ = r_ / 3, kw_ = r_ - 3*kh_; \
    long so0_, so1_; uint32_t sz0_, sz1_; \
    if(IMC == 1){ \
      int hi0 = 2*ho0_ + kh_ - 1, wi0 = 2*wo0_ + kw_ - 1; \
      int hi1 = 2*ho1_ + kh_ - 1, wi1 = 2*wo1_ + kw_ - 1; \
      bool v0 = ((unsigned)hi0 < H1) & ((unsigned)wi0 < W1); \
      bool v1 = ((unsigned)hi1 < H1) & ((unsigned)wi1 < W1); \
      so0_ = v0 ? (((long)(b0_*H1 + hi0)*W1 + wi0)*C1 + cib_ + wseg*8) : 0; \
      so1_ = v1 ? (((long)(b1_*H1 + hi1)*W1 + wi1)*C1 + cib_ + wseg*8) : 0; \
      sz0_ = v0 ? 16u : 0u; sz1_ = v1 ? 16u : 0u; \
    } else { \
      int hi0 = ho0_ + kh_ - 1, wi0 = wo0_ + kw_ - 1; \
      int hi1 = ho1_ + kh_ - 1, wi1 = wo1_ + kw_ - 1; \
      bool v0 = ((unsigned)hi0 < H2) & ((unsigned)wi0 < W2); \
      bool v1 = ((unsigned)hi1 < H2) & ((unsigned)wi1 < W2); \
      so0_ = v0 ? (((long)(b0_*H2 + hi0)*W2 + wi0)*C2 + cib_ + wseg*8) : 0; \
      so1_ = v1 ? (((long)(b1_*H2 + hi1)*W2 + wi1)*C2 + cib_ + wseg*8) : 0; \
      sz0_ = v0 ? 16u : 0u; sz1_ = v1 ? 16u : 0u; \
    } \
    cp16z(stg_ + AHI_O + ls,        g.Ah + so0_, sz0_); \
    cp16z(stg_ + AHI_O + ls + 5120, g.Ah + so1_, sz1_); \
    cp16z(stg_ + ALO_O + ls,        g.Al + so0_, sz0_); \
    cp16z(stg_ + ALO_O + ls + 5120, g.Al + so1_, sz1_); \
  } while(0)

  #define LOAD_CHUNK(c, sidx) do { \
    uint32_t stg_ = smb + (sidx)*STG_B; \
    if(IMC == 0) LOAD_A_DENSE(c, stg_); else LOAD_A_IMC(c, stg_); \
    long gb_ = (long)(tid >> 2)*K + wseg*8 + (long)(c)*32; \
    cp16(stg_ + BHI_O + ls,         Bhb + gb_); \
    cp16(stg_ + BHI_O + ls + 5120,  Bhb + gb_ + K64); \
    cp16(stg_ + BHI_O + ls + 10240, Bhb + gb_ + 2*K64); \
    cp16(stg_ + BHI_O + ls + 15360, Bhb + gb_ + 3*K64); \
    cp16(stg_ + BLO_O + ls,         Blb + gb_); \
    cp16(stg_ + BLO_O + ls + 5120,  Blb + gb_ + K64); \
    cp16(stg_ + BLO_O + ls + 10240, Blb + gb_ + 2*K64); \
    cp16(stg_ + BLO_O + ls + 15360, Blb + gb_ + 3*K64); \
  } while(0)

  LOAD_CHUNK(0, 0); CP_COMMIT();
  LOAD_CHUNK(1, 1); CP_COMMIT();

  for(int c = 0; c < nc; c++){
    CP_WAIT1();
    __syncthreads();
    if(c + 2 < nc){ LOAD_CHUNK(c + 2, (c + 2) % 3); }
    CP_COMMIT();
    uint32_t stg = smb + (c % 3)*STG_B;
    #pragma unroll
    for(int ks = 0; ks < 2; ks++){
      uint32_t ahk[4][4], alk[4][4], bhk[4][4], blk[4][4];
      #pragma unroll
      for(int mt = 0; mt < 4; mt++){
        uint32_t ad = stg + AHI_O + aoff + mt*(16*PITCH*2) + ks*32;
        ldsm4(ahk[mt], ad);
        ldsm4(alk[mt], ad + (ALO_O - AHI_O));
      }
      #pragma unroll
      for(int ng = 0; ng < 4; ng++){
        uint32_t bd = stg + BHI_O + boff + ng*(16*PITCH*2) + ks*32;
        ldsm4(bhk[ng], bd);
        ldsm4(blk[ng], bd + (BLO_O - BHI_O));
      }
      #pragma unroll
      for(int mt = 0; mt < 4; mt++)
        #pragma unroll
        for(int nt = 0; nt < 8; nt++)
          mma_bf16(acc[mt][nt], ahk[mt], &bhk[nt>>1][(nt&1)*2]);
      #pragma unroll
      for(int mt = 0; mt < 4; mt++)
        #pragma unroll
        for(int nt = 0; nt < 8; nt++)
          mma_bf16(acc[mt][nt], ahk[mt], &blk[nt>>1][(nt&1)*2]);
      #pragma unroll
      for(int mt = 0; mt < 4; mt++)
        #pragma unroll
        for(int nt = 0; nt < 8; nt++)
          mma_bf16(acc[mt][nt], alk[mt], &bhk[nt>>1][(nt&1)*2]);
    }
  }

  // ---- epilogue ----
  int mrow = lane >> 2;
  int ncol = (lane & 3) * 2;
  #pragma unroll
  for(int mt = 0; mt < 4; mt++){
    #pragma unroll
    for(int nt = 0; nt < 8; nt++){
      #pragma unroll
      for(int hf = 0; hf < 2; hf++){
        long gm = m0 + wm*64 + mt*16 + mrow + hf*8;
        int  gn = n0 + wn*64 + nt*8 + ncol;
        float v0 = acc[mt][nt][hf*2+0];
        float v1 = acc[mt][nt][hf*2+1];
        if(OUT == 2){
          int seg = gn >> 9, col = gn & 511;
          if(seg == 0)      *(float2*)&g.Co[gm*DIM + col] = make_float2(v0, v1);
          else if(seg == 1) *(float2*)&g.Cv[gm*DIM + col] = make_float2(v0, v1);
          else              *(float2*)&g.Cr[gm*DIM + col] = make_float2(sgm(v0), sgm(v1));
        } else if(OUT == 3){
          if(gn < HID){
            v0 = fmaxf(v0, 0.f); v0 *= v0;
            v1 = fmaxf(v1, 0.f); v1 *= v1;
            uint32_t hh, ll;
            split2(v0, v1, hh, ll);
            *(uint32_t*)&g.Ch[gm*HID + gn] = hh;
            *(uint32_t*)&g.Cl[gm*HID + gn] = ll;
          } else {
            *(float2*)&g.Cr[gm*DIM + (gn - HID)] = make_float2(sgm(v0), sgm(v1));
          }
        } else {
          if(g.bias){ v0 += g.bias[gn]; v1 += g.bias[gn+1]; }
          if(ACT == 1){ v0 = fmaxf(v0,0.f); v1 = fmaxf(v1,0.f); }
          else if(ACT == 2){ v0 = sgm(v0); v1 = sgm(v1); }
          else if(ACT == 3){ v0 = fmaxf(v0,0.f); v0 *= v0; v1 = fmaxf(v1,0.f); v1 *= v1; }
          if(OUT == 0){
            float* cp = g.Co + gm*N + gn;
            if(EPI == 1){ v0 += cp[0]; v1 += cp[1]; }
            else if(EPI == 2){
              const float* mp = g.mul + gm*N + gn;
              v0 = cp[0] + mp[0]*v0; v1 = cp[1] + mp[1]*v1;
            }
            *(float2*)cp = make_float2(v0, v1);
          } else {
            uint32_t hh, ll;
            split2(v0, v1, hh, ll);
            *(uint32_t*)&g.Ch[gm*N + gn] = hh;
            *(uint32_t*)&g.Cl[gm*N + gn] = ll;
          }
        }
      }
    }
  }
}

// ---------------- conv1: direct, split bf16 output ----------------------------
__global__ void conv1_k(const float* __restrict__ x, const float* __restrict__ w,
                        const float* __restrict__ bias){
  int t = blockIdx.x*256 + threadIdx.x;
  int co = t & 127;
  int rest = t >> 7;
  int wo = rest % W1; rest /= W1;
  int ho = rest % H1; int b = rest / H1;
  float acc = bias[co];
  int hi0 = 2*ho - 1, wi0 = 2*wo - 1;
  #pragma unroll
  for(int kh=0; kh<3; kh++){
    int hi = hi0 + kh;
    if(hi < 0 || hi >= LEN) continue;
    #pragma unroll
    for(int kw=0; kw<3; kw++){
      int wi = wi0 + kw;
      if(wi < 0 || wi >= FREQ) continue;
      acc = fmaf(x[(hi + (long)b*LEN)*FREQ + wi], w[co*9 + kh*3 + kw], acc);
    }
  }
  acc = fmaxf(acc, 0.f);
  bf h = __float2bfloat16(acc);
  g_c1h[t] = h;
  g_c1l[t] = __float2bfloat16(acc - __bfloat162float(h));
}

// ---------------- conv weight prep --------------------------------------------
__global__ void prep_conv_k(const float* __restrict__ w2, const float* __restrict__ w3){
  int t = blockIdx.x*256 + threadIdx.x;
  if(t < C2*K2C){
    int co = t / K2C; int idx = t % K2C;
    int r = idx / C1; int ci = idx % C1;
    float v = w2[co*(C1*9) + ci*9 + r];
    bf h = __float2bfloat16(v);
    g_w2Th[t] = h; g_w2Tl[t] = __float2bfloat16(v - __bfloat162float(h));
  } else {
    int u = t - C2*K2C;
    if(u >= C3*K3C) return;
    int co = u / K3C; int idx = u % K3C;
    int r = idx / C2; int ci = idx % C2;
    float v = w3[co*(C2*9) + ci*9 + r];
    bf h = __float2bfloat16(v);
    g_w3Th[u] = h; g_w3Tl[u] = __float2bfloat16(v - __bfloat162float(h));
  }
}

// ------ big weight prep: transpose [R][C]->[C][R] + split + concat ------------
__global__ void prep_big_k(const float* __restrict__ embed_w,
                           const float* __restrict__ awk, const float* __restrict__ awv,
                           const float* __restrict__ awr, const float* __restrict__ awo,
                           const float* __restrict__ fwr, const float* __restrict__ fwk,
                           const float* __restrict__ fwv){
  int t = blockIdx.x;
  const float* in; bf *oh, *ol; int R, C, tr, tc;
  if(t < 5120){
    in = embed_w; oh = g_ewTh; ol = g_ewTl; R = KE; C = DIM;
    tr = t / 16; tc = t % 16;
  } else {
    int u = t - 5120;
    int i = u / 3328; int v = u % 3328;
    long o2 = (long)i*DIM*DIM, oh2 = (long)i*DIM*HID;
    long qb = (long)i*3*DIM*DIM, fb = (long)i*(HID+DIM)*DIM;
    if(v < 768){
      int kind = v / 256; int vv = v % 256;
      R = DIM; C = DIM; tr = vv / 16; tc = vv % 16;
      in = (kind == 0 ? awk : kind == 1 ? awv : awr) + o2;
      oh = g_aqkvTh + qb + (long)kind*DIM*DIM;
      ol = g_aqkvTl + qb + (long)kind*DIM*DIM;
    } else if(v < 1024){
      int vv = v - 768;
      R = DIM; C = DIM; tr = vv / 16; tc = vv % 16;
      in = awo + o2; oh = g_awoTh + o2; ol = g_awoTl + o2;
    } else if(v < 2048){
      int vv = v - 1024;
      R = DIM; C = HID; tr = vv / 64; tc = vv % 64;
      in = fwk + oh2; oh = g_fkrTh + fb; ol = g_fkrTl + fb;
    } else if(v < 2304){
      int vv = v - 2048;
      R = DIM; C = DIM; tr = vv / 16; tc = vv % 16;
      in = fwr + o2;
      oh = g_fkrTh + fb + (long)HID*DIM;
      ol = g_fkrTl + fb + (long)HID*DIM;
    } else {
      int vv = v - 2304;
      R = HID; C = DIM; tr = vv / 16; tc = vv % 16;
      in = fwv + oh2; oh = g_fwvTh + oh2; ol = g_fwvTl + oh2;
    }
  }
  __shared__ float tile[32][33];
  int r0 = tr*32, c0 = tc*32;
  int x = c0 + threadIdx.x;
  for(int dy = threadIdx.y; dy < 32; dy += 8)
    tile[dy][threadIdx.x] = in[(long)(r0 + dy)*C + x];
  __syncthreads();
  int xo = r0 + threadIdx.x;
  for(int dy = threadIdx.y; dy < 32; dy += 8){
    float v = tile[threadIdx.x][dy];
    bf h = __float2bfloat16(v);
    long oidx = (long)(c0 + dy)*R + xo;
    oh[oidx] = h; ol[oidx] = __float2bfloat16(v - __bfloat162float(h));
  }
}

// ---------------- reshape (b,u,w,c) -> (b,u, c*20+w), bf16 pair ----------------
__global__ void reshape_k(){
  __shared__ uint16_t smh[KE], sml[KE];
  int m = blockIdx.x;
  const uint16_t* srch = (const uint16_t*)g_c3h + (long)m*KE;
  const uint16_t* srcl = (const uint16_t*)g_c3l + (long)m*KE;
  for(int i=threadIdx.x; i<KE; i+=256){
    int w = i / 512, c = i & 511;
    int d = c*W2 + w;
    smh[d] = srch[i];
    sml[d] = srcl[i];
  }
  __syncthreads();
  uint16_t* dsth = (uint16_t*)g_yrh + (long)m*KE;
  uint16_t* dstl = (uint16_t*)g_yrl + (long)m*KE;
  for(int i=threadIdx.x; i<KE; i+=256){ dsth[i] = smh[i]; dstl[i] = sml[i]; }
}

// ---------------- LayerNorm -----------------------------------------------------
__global__ void ln_k(const float* __restrict__ x, const float* __restrict__ gw,
                     const float* __restrict__ gb, float* __restrict__ o){
  int m = blockIdx.x;
  int tid = threadIdx.x;
  const float* xr = x + (long)m*DIM;
  float v[4]; float s = 0.f, sq = 0.f;
  #pragma unroll
  for(int j=0;j<4;j++){ float t = xr[tid + j*128]; v[j] = t; s += t; sq += t*t; }
  #pragma unroll
  for(int off=16; off; off>>=1){
    s  += __shfl_xor_sync(0xffffffffu, s,  off);
    sq += __shfl_xor_sync(0xffffffffu, sq, off);
  }
  __shared__ float ss[4], sqs[4];
  if((tid & 31) == 0){ ss[tid>>5] = s; sqs[tid>>5] = sq; }
  __syncthreads();
  s  = (ss[0]+ss[1]) + (ss[2]+ss[3]);
  sq = (sqs[0]+sqs[1]) + (sqs[2]+sqs[3]);
  float mean = s * (1.f/DIM);
  float var  = sq * (1.f/DIM) - mean*mean;
  float rstd = rsqrtf(var + 1e-5f);
  float* orow = o + (long)m*DIM;
  #pragma unroll
  for(int j=0;j<4;j++){
    int d = tid + j*128;
    orow[d] = (v[j] - mean)*rstd*gw[d] + gb[d];
  }
}

// ---------------- time-shift mixes ----------------------------------------------
__global__ void mix3_k(const float* __restrict__ xn, const float* __restrict__ mk,
                       const float* __restrict__ mv, const float* __restrict__ mr){
  int g = blockIdx.x*256 + threadIdx.x;
  int t = g*2;
  int d = t & (DIM-1);
  int tok = (t >> 9) & (USEQ-1);
  float2 cur = *(const float2*)&xn[t];
  float2 sh = tok ? *(const float2*)&xn[t - DIM] : make_float2(0.f, 0.f);
  float d0 = cur.x - sh.x, d1 = cur.y - sh.y;
  uint32_t h, l;
  split2(fmaf(d0, mk[d], sh.x), fmaf(d1, mk[d+1], sh.y), h, l);
  *(uint32_t*)&g_xkh[t] = h; *(uint32_t*)&g_xkl[t] = l;
  split2(fmaf(d0, mv[d], sh.x), fmaf(d1, mv[d+1], sh.y), h, l);
  *(uint32_t*)&g_xvh[t] = h; *(uint32_t*)&g_xvl[t] = l;
  split2(fmaf(d0, mr[d], sh.x), fmaf(d1, mr[d+1], sh.y), h, l);
  *(uint32_t*)&g_xrh[t] = h; *(uint32_t*)&g_xrl[t] = l;
}
__global__ void mix2_k(const float* __restrict__ xn, const float* __restrict__ mk,
                       const float* __restrict__ mr){
  int g = blockIdx.x*256 + threadIdx.x;
  int t = g*2;
  int d = t & (DIM-1);
  int tok = (t >> 9) & (USEQ-1);
  float2 cur = *(const float2*)&xn[t];
  float2 sh = tok ? *(const float2*)&xn[t - DIM] : make_float2(0.f, 0.f);
  float d0 = cur.x - sh.x, d1 = cur.y - sh.y;
  uint32_t h, l;
  split2(fmaf(d0, mk[d], sh.x), fmaf(d1, mk[d+1], sh.y), h, l);
  *(uint32_t*)&g_xkh[t] = h; *(uint32_t*)&g_xkl[t] = l;
  split2(fmaf(d0, mr[d], sh.x), fmaf(d1, mr[d+1], sh.y), h, l);
  *(uint32_t*)&g_xrh[t] = h; *(uint32_t*)&g_xrl[t] = l;
}

// ---------------- WKV scan, pipelined, bf16 split output ------------------------
#define WG 8
__device__ __forceinline__ void wkv_load(const float* kp, const float* vp,
                                         const float* rp, long off0,
                                         float* kb, float* vb, float* rb){
  #pragma unroll
  for(int j=0;j<WG;j++){
    long off = off0 + (long)j*DIM;
    kb[j] = __ldg(kp + off); vb[j] = __ldg(vp + off); rb[j] = __ldg(rp + off);
  }
}
__device__ __forceinline__ void wkv_step(float* kb, float* vb, float* rb,
                                         bf* oh, bf* ol, long off0,
                                         float w, float u,
                                         float& aa, float& bb, float& pp){
  #pragma unroll
  for(int j=0;j<WG;j++){
    float kt = kb[j], vt = vb[j];
    float ww = u + kt;
    float p  = fmaxf(pp, ww);
    float e1 = __expf(pp - p), e2 = __expf(ww - p);
    float o  = rb[j] * (e1*aa + e2*vt) / (e1*bb + e2);
    bf h = __float2bfloat16(o);
    long off = off0 + (long)j*DIM;
    oh[off] = h;
    ol[off] = __float2bfloat16(o - __bfloat162float(h));
    float ww2 = pp + w;
    float p2  = fmaxf(ww2, kt);
    e1 = __expf(ww2 - p2); e2 = __expf(kt - p2);
    aa = e1*aa + e2*vt; bb = e1*bb + e2; pp = p2;
  }
}
__global__ void wkv_k(const float* __restrict__ k, const float* __restrict__ v,
                      const float* __restrict__ r,
                      const float* __restrict__ dec, const float* __restrict__ fir){
  int t = blockIdx.x*blockDim.x + threadIdx.x;
  int d = t & (DIM-1); int b = t >> 9;
  float w = -__expf(dec[d]);
  float u = fir[d];
  float aa = 0.f, bb = 0.f, pp = -1e38f;
  long base = (long)b*USEQ*DIM + d;
  const float* kp = k + base;
  const float* vp = v + base;
  const float* rp = r + base;
  bf* oh = g_rwh + base;
  bf* ol = g_rwl + base;
  const int NG = USEQ/WG;
  float k0b[WG], v0b[WG], r0b[WG];
  float k1b[WG], v1b[WG], r1b[WG];
  wkv_load(kp, vp, rp, 0, k0b, v0b, r0b);
  for(int g=0; g<NG; g+=2){
    long off1 = (long)(g+1)*WG*DIM;
    wkv_load(kp, vp, rp, off1, k1b, v1b, r1b);
    wkv_step(k0b, v0b, r0b, oh, ol, (long)g*WG*DIM, w, u, aa, bb, pp);
    if(g+2 < NG){
      long off2 = (long)(g+2)*WG*DIM;
      wkv_load(kp, vp, rp, off2, k0b, v0b, r0b);
    }
    wkv_step(k1b, v1b, r1b, oh, ol, off1, w, u, aa, bb, pp);
  }
}

// ---------------- olens tail -----------------------------------------------------
__global__ void tail_k(const int* __restrict__ x_len, float* __restrict__ out, int out_size){
  int b = threadIdx.x;
  if(b < BATCH && out_size >= HTOK + BATCH){
    int l1 = (x_len[b] - 1)/2 + 1;
    int ol = (l1 - 1)/2 + 1;
    out[HTOK + b] = (float)ol;
  }
}

// ---------------- host side ------------------------------------------------------
template <typename T>
static void* symaddr(const T& s){ void* p = nullptr; cudaGetSymbolAddress(&p, s); return p; }

template<int ACT, int EPI, int OUT, int IMC>
static void gemm(int M, int N, int K, const GP& g){
  cudaFuncSetAttribute(mgemm_k<ACT,EPI,OUT,IMC>, cudaFuncAttributeMaxDynamicSharedMemorySize, MSMEM);
  dim3 grid(N/256, M/128);
  mgemm_k<ACT,EPI,OUT,IMC><<<grid, 256, MSMEM>>>(M, N, K, g);
}

extern "C" void kernel_launch(void* const* d_in, const int* in_sizes, int n_in,
                              void* d_out, int out_size){
  const float* x       = (const float*)d_in[0];
  const int*   x_len   = (const int*)  d_in[1];
  const float* conv1_w = (const float*)d_in[2];
  const float* conv1_b = (const float*)d_in[3];
  const float* conv2_w = (const float*)d_in[4];
  const float* conv2_b = (const float*)d_in[5];
  const float* conv3_w = (const float*)d_in[6];
  const float* conv3_b = (const float*)d_in[7];
  const float* embed_w = (const float*)d_in[8];
  const float* embed_b = (const float*)d_in[9];
  const float* eln_g   = (const float*)d_in[10];
  const float* eln_b   = (const float*)d_in[11];
  const float* lag     = (const float*)d_in[12];
  const float* lab     = (const float*)d_in[13];
  const float* dec     = (const float*)d_in[14];
  const float* fir     = (const float*)d_in[15];
  const float* amk     = (const float*)d_in[16];
  const float* amv     = (const float*)d_in[17];
  const float* amr     = (const float*)d_in[18];
  const float* awk     = (const float*)d_in[19];
  const float* awv     = (const float*)d_in[20];
  const float* awr     = (const float*)d_in[21];
  const float* awo     = (const float*)d_in[22];
  const float* lfg     = (const float*)d_in[23];
  const float* lfb     = (const float*)d_in[24];
  const float* fmk     = (const float*)d_in[25];
  const float* fmr     = (const float*)d_in[26];
  const float* fwk     = (const float*)d_in[27];
  const float* fwv     = (const float*)d_in[28];
  const float* fwr     = (const float*)d_in[29];
  const float* flg     = (const float*)d_in[30];
  const float* flb     = (const float*)d_in[31];
  float* out = (float*)d_out;

  bf* p_c1h = (bf*)symaddr(g_c1h); bf* p_c1l = (bf*)symaddr(g_c1l);
  bf* p_c2h = (bf*)symaddr(g_c2h); bf* p_c2l = (bf*)symaddr(g_c2l);
  bf* p_c3h = (bf*)symaddr(g_c3h); bf* p_c3l = (bf*)symaddr(g_c3l);
  bf* p_yrh = (bf*)symaddr(g_yrh); bf* p_yrl = (bf*)symaddr(g_yrl);
  float* p_t0 = (float*)symaddr(g_t0);
  float* p_h  = (float*)symaddr(g_h);
  float* p_xn = (float*)symaddr(g_xn);
  bf* p_xkh = (bf*)symaddr(g_xkh); bf* p_xkl = (bf*)symaddr(g_xkl);
  bf* p_xvh = (bf*)symaddr(g_xvh); bf* p_xvl = (bf*)symaddr(g_xvl);
  bf* p_xrh = (bf*)symaddr(g_xrh); bf* p_xrl = (bf*)symaddr(g_xrl);
  float* p_k = (float*)symaddr(g_k);
  float* p_v = (float*)symaddr(g_v);
  float* p_r = (float*)symaddr(g_r);
  bf* p_rwh = (bf*)symaddr(g_rwh); bf* p_rwl = (bf*)symaddr(g_rwl);
  bf* p_kkh = (bf*)symaddr(g_kkh); bf* p_kkl = (bf*)symaddr(g_kkl);
  bf* p_w2Th = (bf*)symaddr(g_w2Th); bf* p_w2Tl = (bf*)symaddr(g_w2Tl);
  bf* p_w3Th = (bf*)symaddr(g_w3Th); bf* p_w3Tl = (bf*)symaddr(g_w3Tl);
  bf* p_ewTh = (bf*)symaddr(g_ewTh); bf* p_ewTl = (bf*)symaddr(g_ewTl);
  bf* p_aqkvTh = (bf*)symaddr(g_aqkvTh); bf* p_aqkvTl = (bf*)symaddr(g_aqkvTl);
  bf* p_awoTh  = (bf*)symaddr(g_awoTh);  bf* p_awoTl  = (bf*)symaddr(g_awoTl);
  bf* p_fkrTh  = (bf*)symaddr(g_fkrTh);  bf* p_fkrTl  = (bf*)symaddr(g_fkrTl);
  bf* p_fwvTh  = (bf*)symaddr(g_fwvTh);  bf* p_fwvTl  = (bf*)symaddr(g_fwvTl);

  // launches 1-6 (launch 6 = conv3 implicit-im2col GEMM profiled by ncu -s 5 -c 1)
  prep_conv_k<<<(C2*K2C + C3*K3C + 255)/256, 256>>>(conv2_w, conv3_w);
  conv1_k<<<(BATCH*H1*W1*C1)/256, 256>>>(x, conv1_w, conv1_b);
  prep_big_k<<<18432, dim3(32,8)>>>(embed_w, awk, awv, awr, awo, fwr, fwk, fwv);
  tail_k<<<1, 32>>>(x_len, out, out_size);
  { GP g = gp0(); g.Ah = p_c1h; g.Al = p_c1l; g.Bh = p_w2Th; g.Bl = p_w2Tl;
    g.bias = conv2_b; g.Ch = p_c2h; g.Cl = p_c2l;
    gemm<1,0,1,1>(MCONV, C2, K2C, g); }
  { GP g = gp0(); g.Ah = p_c2h; g.Al = p_c2l; g.Bh = p_w3Th; g.Bl = p_w3Tl;
    g.bias = conv3_b; g.Ch = p_c3h; g.Cl = p_c3l;
    gemm<1,0,1,2>(MCONV, C3, K3C, g); }

  reshape_k<<<MT, 256>>>();
  { GP g = gp0(); g.Ah = p_yrh; g.Al = p_yrl; g.Bh = p_ewTh; g.Bl = p_ewTl;
    g.bias = embed_b; g.Co = p_t0;
    gemm<0,0,0,0>(MT, DIM, KE, g); }
  ln_k<<<MT, 128>>>(p_t0, eln_g, eln_b, p_h);

  // ---- RWKV blocks ----
  for(int i = 0; i < NB_; i++){
    long w2 = (long)i*DIM*DIM;
    long wh = (long)i*DIM*HID;
    long qb = (long)i*3*DIM*DIM;
    long fb = (long)i*(HID+DIM)*DIM;
    // time mixing: ln + mix, fused QKV GEMM (A per N-segment)
    ln_k<<<MT, 128>>>(p_h, lag + i*DIM, lab + i*DIM, p_xn);
    mix3_k<<<HTOK/512, 256>>>(p_xn, amk + i*DIM, amv + i*DIM, amr + i*DIM);
    { GP g = gp0(); g.Ah = p_xkh; g.Al = p_xkl; g.A2h = p_xvh; g.A2l = p_xvl;
      g.A3h = p_xrh; g.A3l = p_xrl; g.Bh = p_aqkvTh + qb; g.Bl = p_aqkvTl + qb;
      g.Co = p_k; g.Cv = p_v; g.Cr = p_r;
      gemm<0,0,2,0>(MT, 3*DIM, DIM, g); }
    wkv_k<<<(BATCH*DIM)/32, 32>>>(p_k, p_v, p_r, dec + i*DIM, fir + i*DIM);
    { GP g = gp0(); g.Ah = p_rwh; g.Al = p_rwl;
      g.Bh = p_awoTh + w2; g.Bl = p_awoTl + w2; g.Co = p_h;
      gemm<0,1,0,0>(MT, DIM, DIM, g); }
    // channel mixing: ln + mix, fused FFN(k,r) GEMM
    ln_k<<<MT, 128>>>(p_h, lfg + i*DIM, lfb + i*DIM, p_xn);
    mix2_k<<<HTOK/512, 256>>>(p_xn, fmk + i*DIM, fmr + i*DIM);
    { GP g = gp0(); g.Ah = p_xkh; g.Al = p_xkl; g.A3h = p_xrh; g.A3l = p_xrl;
      g.Bh = p_fkrTh + fb; g.Bl = p_fkrTl + fb;
      g.Cr = p_r; g.Ch = p_kkh; g.Cl = p_kkl;
      gemm<0,0,3,0>(MT, HID+DIM, DIM, g); }
    { GP g = gp0(); g.Ah = p_kkh; g.Al = p_kkl;
      g.Bh = p_fwvTh + wh; g.Bl = p_fwvTl + wh; g.Co = p_h; g.mul = p_r;
      gemm<0,2,0,0>(MT, DIM, HID, g); }
  }

  ln_k<<<MT, 128>>>(p_h, flg, flb, out);
  tail_k<<<1, 32>>>(x_len, out, out_size);
}

// round 17
// speedup vs baseline: 1.0205x; 1.0205x over previous
#include <cuda_runtime.h>
#include <cuda_bf16.h>
#include <cstdint>

typedef __nv_bfloat16 bf;

#define NB_   4
#define BATCH 8
#define LEN   4096
#define FREQ  80
#define DIM   512
#define HID   2048
#define USEQ  1024
#define C1    128
#define C2    256
#define C3    512
#define H1    2048
#define W1    40
#define H2    1024
#define W2    20
#define MCONV (BATCH*H2*W2)      /* 163840 */
#define K2C   (9*C1)             /* 1152 */
#define K3C   (9*C2)             /* 2304 */
#define KE    (C3*W2)            /* 10240 */
#define MT    (BATCH*USEQ)       /* 8192 */
#define HTOK  (MT*DIM)           /* 4194304 */

// ---------------- scratch (device globals; no allocations) ----------------
__device__ bf g_c1h[BATCH*H1*W1*C1], g_c1l[BATCH*H1*W1*C1];
__device__ bf g_c2h[MCONV*C2],     g_c2l[MCONV*C2];
__device__ bf g_c3h[MCONV*C3],     g_c3l[MCONV*C3];
__device__ float g_t0[HTOK];
__device__ float g_h[HTOK];
__device__ float g_xn[HTOK];
__device__ bf g_xkh[HTOK], g_xkl[HTOK];
__device__ bf g_xvh[HTOK], g_xvl[HTOK];
__device__ bf g_xrh[HTOK], g_xrl[HTOK];
__device__ float g_k[HTOK];
__device__ float g_v[HTOK];
__device__ float g_r[HTOK];
__device__ bf g_rwh[HTOK], g_rwl[HTOK];
__device__ bf g_kkh[MT*HID], g_kkl[MT*HID];
// transposed+split weights, [N][K] K-major bf16 hi/lo
__device__ bf g_w2Th[C2*K2C],  g_w2Tl[C2*K2C];
__device__ bf g_w3Th[C3*K3C],  g_w3Tl[C3*K3C];
__device__ bf g_ewTh[DIM*KE],  g_ewTl[DIM*KE];   // [n][k'], k' = w*512+c (permuted!)
__device__ bf g_aqkvTh[NB_*3*DIM*DIM], g_aqkvTl[NB_*3*DIM*DIM];
__device__ bf g_awoTh[NB_*DIM*DIM],    g_awoTl[NB_*DIM*DIM];
__device__ bf g_fkrTh[NB_*(HID+DIM)*DIM], g_fkrTl[NB_*(HID+DIM)*DIM];
__device__ bf g_fwvTh[NB_*DIM*HID],    g_fwvTl[NB_*DIM*HID];

// ================== helpers ==================
__device__ __forceinline__ uint32_t smem_to_u32(const void* p) {
  uint32_t a;
  asm("{ .reg .u64 t; cvta.to.shared.u64 t, %1; cvt.u32.u64 %0, t; }"
      : "=r"(a) : "l"(p));
  return a;
}
__device__ __forceinline__ void ldsm4(uint32_t* r, uint32_t addr){
  asm volatile("ldmatrix.sync.aligned.m8n8.x4.shared.b16 {%0,%1,%2,%3}, [%4];"
    : "=r"(r[0]),"=r"(r[1]),"=r"(r[2]),"=r"(r[3]) : "r"(addr));
}
__device__ __forceinline__ void mma_bf16(float* d, const uint32_t* a, const uint32_t* b){
  asm volatile("mma.sync.aligned.m16n8k16.row.col.f32.bf16.bf16.f32 "
    "{%0,%1,%2,%3}, {%4,%5,%6,%7}, {%8,%9}, {%0,%1,%2,%3};"
    : "+f"(d[0]),"+f"(d[1]),"+f"(d[2]),"+f"(d[3])
    : "r"(a[0]),"r"(a[1]),"r"(a[2]),"r"(a[3]), "r"(b[0]),"r"(b[1]));
}
__device__ __forceinline__ void cp16(uint32_t s, const void* g){
  asm volatile("cp.async.cg.shared.global [%0], [%1], 16;" :: "r"(s), "l"(g));
}
__device__ __forceinline__ void cp16z(uint32_t s, const void* g, uint32_t sz){
  asm volatile("cp.async.cg.shared.global [%0], [%1], 16, %2;" :: "r"(s), "l"(g), "r"(sz));
}
#define CP_COMMIT() asm volatile("cp.async.commit_group;" ::: "memory")
#define CP_WAIT1()  asm volatile("cp.async.wait_group 1;" ::: "memory")

__device__ __forceinline__ void split2(float v0, float v1, uint32_t& h, uint32_t& l){
  __nv_bfloat162 hh = __floats2bfloat162_rn(v0, v1);
  float r0 = v0 - __bfloat162float(hh.x);
  float r1 = v1 - __bfloat162float(hh.y);
  __nv_bfloat162 ll = __floats2bfloat162_rn(r0, r1);
  h = *(uint32_t*)&hh; l = *(uint32_t*)&ll;
}
__device__ __forceinline__ float sgm(float v){ return 1.f/(1.f + __expf(-v)); }

// ---------------- GEMM pointer bundle ------------------------------------------
struct GP {
  const bf* Ah;  const bf* Al;
  const bf* Bh;  const bf* Bl;
  const float* bias;
  float* Co;
  bf* Ch; bf* Cl;
  const float* mul;
};
static inline GP gp0(){
  GP g; g.Ah=nullptr; g.Al=nullptr; g.Bh=nullptr; g.Bl=nullptr; g.bias=nullptr;
  g.Co=nullptr; g.Ch=nullptr; g.Cl=nullptr; g.mul=nullptr;
  return g;
}

// ====== bf16x3 MMA GEMM: CTA 128x256, Kchunk=32, 8 warps (64x64 tiles) =======
// 3-stage cp.async pipeline, register-lean flat loader.
// ACT: 0 none,1 relu,2 sigmoid,3 relu^2 ; EPI: 0 store,1 +=,2 Co+mul*acc
// OUT: 0 fp32 Co ; 1 bf16 split Ch/Cl
// IMC: 0 dense A rows ; 1 implicit im2col from conv1 output (c1, 3x3 s2)
//      2 implicit im2col from conv2 output (c2, 3x3 s1)
#define PITCH 40
#define AHI_O 0
#define ALO_O 10240
#define BHI_O 20480
#define BLO_O 40960
#define STG_B 61440
#define MSMEM (3*STG_B)

template<int ACT, int EPI, int OUT, int IMC>
__global__ void __launch_bounds__(256, 1) mgemm_k(int M, int N, int K, GP g){
  extern __shared__ char smarr[];
  uint32_t smb = smem_to_u32(smarr);
  int tid = threadIdx.x, lane = tid & 31, wid = tid >> 5;
  int wm = wid >> 2, wn = wid & 3;          // warp grid 2(m) x 4(n), tiles 64x64
  long m0 = (long)blockIdx.y * 128;
  int  n0 = blockIdx.x * 256;

  const bf* Ahb = g.Ah + m0*(long)K;
  const bf* Alb = g.Al + m0*(long)K;
  const bf* Bhb = g.Bh + (long)n0*K;
  const bf* Blb = g.Bl + (long)n0*K;
  int wseg = tid & 3;
  long lg = (long)(tid >> 2)*K + wseg*8;
  uint32_t ls = (uint32_t)(tid >> 2)*80 + wseg*16;
  long K64 = (long)K*64;

  // implicit im2col per-row decode (output spatial = H2 x W2 for both convs)
  int b0_=0, ho0_=0, wo0_=0, b1_=0, ho1_=0, wo1_=0;
  if(IMC != 0){
    long mA0 = m0 + (tid >> 2);
    long mA1 = mA0 + 64;
    wo0_ = (int)(mA0 % W2); ho0_ = (int)((mA0 / W2) % H2); b0_ = (int)(mA0 / (W2*H2));
    wo1_ = (int)(mA1 % W2); ho1_ = (int)((mA1 / W2) % H2); b1_ = (int)(mA1 / (W2*H2));
  }

  uint32_t aoff = (((uint32_t)wm*64 + ((lane>>3)&1)*8 + (lane&7))*PITCH + ((lane>>4)&1)*8) * 2;
  uint32_t boff = (((uint32_t)wn*64 + ((lane>>4)&1)*8 + (lane&7))*PITCH + ((lane>>3)&1)*8) * 2;

  float acc[4][8][4];
  #pragma unroll
  for(int i=0;i<4;i++)
    #pragma unroll
    for(int j=0;j<8;j++)
      #pragma unroll
      for(int q=0;q<4;q++) acc[i][j][q] = 0.f;

  int nc = K >> 5;

  #define LOAD_A_DENSE(c, stg_) do { \
    long go_ = lg + (long)(c)*32; \
    cp16(stg_ + AHI_O + ls,         Ahb + go_); \
    cp16(stg_ + AHI_O + ls + 5120,  Ahb + go_ + K64); \
    cp16(stg_ + ALO_O + ls,         Alb + go_); \
    cp16(stg_ + ALO_O + ls + 5120,  Alb + go_ + K64); \
  } while(0)

  #define LOAD_A_IMC(c, stg_) do { \
    int r_, cib_; \
    if(IMC == 1){ r_ = (c) >> 2; cib_ = ((c) & 3) << 5; } \
    else        { r_ = (c) >> 3; cib_ = ((c) & 7) << 5; } \
    int kh_ = r_ / 3, kw_ = r_ - 3*kh_; \
    long so0_, so1_; uint32_t sz0_, sz1_; \
    if(IMC == 1){ \
      int hi0 = 2*ho0_ + kh_ - 1, wi0 = 2*wo0_ + kw_ - 1; \
      int hi1 = 2*ho1_ + kh_ - 1, wi1 = 2*wo1_ + kw_ - 1; \
      bool v0 = ((unsigned)hi0 < H1) & ((unsigned)wi0 < W1); \
      bool v1 = ((unsigned)hi1 < H1) & ((unsigned)wi1 < W1); \
      so0_ = v0 ? (((long)(b0_*H1 + hi0)*W1 + wi0)*C1 + cib_ + wseg*8) : 0; \
      so1_ = v1 ? (((long)(b1_*H1 + hi1)*W1 + wi1)*C1 + cib_ + wseg*8) : 0; \
      sz0_ = v0 ? 16u : 0u; sz1_ = v1 ? 16u : 0u; \
    } else { \
      int hi0 = ho0_ + kh_ - 1, wi0 = wo0_ + kw_ - 1; \
      int hi1 = ho1_ + kh_ - 1, wi1 = wo1_ + kw_ - 1; \
      bool v0 = ((unsigned)hi0 < H2) & ((unsigned)wi0 < W2); \
      bool v1 = ((unsigned)hi1 < H2) & ((unsigned)wi1 < W2); \
      so0_ = v0 ? (((long)(b0_*H2 + hi0)*W2 + wi0)*C2 + cib_ + wseg*8) : 0; \
      so1_ = v1 ? (((long)(b1_*H2 + hi1)*W2 + wi1)*C2 + cib_ + wseg*8) : 0; \
      sz0_ = v0 ? 16u : 0u; sz1_ = v1 ? 16u : 0u; \
    } \
    cp16z(stg_ + AHI_O + ls,        g.Ah + so0_, sz0_); \
    cp16z(stg_ + AHI_O + ls + 5120, g.Ah + so1_, sz1_); \
    cp16z(stg_ + ALO_O + ls,        g.Al + so0_, sz0_); \
    cp16z(stg_ + ALO_O + ls + 5120, g.Al + so1_, sz1_); \
  } while(0)

  #define LOAD_CHUNK(c, sidx) do { \
    uint32_t stg_ = smb + (sidx)*STG_B; \
    if(IMC == 0) LOAD_A_DENSE(c, stg_); else LOAD_A_IMC(c, stg_); \
    long gb_ = (long)(tid >> 2)*K + wseg*8 + (long)(c)*32; \
    cp16(stg_ + BHI_O + ls,         Bhb + gb_); \
    cp16(stg_ + BHI_O + ls + 5120,  Bhb + gb_ + K64); \
    cp16(stg_ + BHI_O + ls + 10240, Bhb + gb_ + 2*K64); \
    cp16(stg_ + BHI_O + ls + 15360, Bhb + gb_ + 3*K64); \
    cp16(stg_ + BLO_O + ls,         Blb + gb_); \
    cp16(stg_ + BLO_O + ls + 5120,  Blb + gb_ + K64); \
    cp16(stg_ + BLO_O + ls + 10240, Blb + gb_ + 2*K64); \
    cp16(stg_ + BLO_O + ls + 15360, Blb + gb_ + 3*K64); \
  } while(0)

  LOAD_CHUNK(0, 0); CP_COMMIT();
  LOAD_CHUNK(1, 1); CP_COMMIT();

  for(int c = 0; c < nc; c++){
    CP_WAIT1();
    __syncthreads();
    if(c + 2 < nc){ LOAD_CHUNK(c + 2, (c + 2) % 3); }
    CP_COMMIT();
    uint32_t stg = smb + (c % 3)*STG_B;
    #pragma unroll
    for(int ks = 0; ks < 2; ks++){
      uint32_t ahk[4][4], alk[4][4], bhk[4][4], blk[4][4];
      #pragma unroll
      for(int mt = 0; mt < 4; mt++){
        uint32_t ad = stg + AHI_O + aoff + mt*(16*PITCH*2) + ks*32;
        ldsm4(ahk[mt], ad);
        ldsm4(alk[mt], ad + (ALO_O - AHI_O));
      }
      #pragma unroll
      for(int ng = 0; ng < 4; ng++){
        uint32_t bd = stg + BHI_O + boff + ng*(16*PITCH*2) + ks*32;
        ldsm4(bhk[ng], bd);
        ldsm4(blk[ng], bd + (BLO_O - BHI_O));
      }
      #pragma unroll
      for(int mt = 0; mt < 4; mt++)
        #pragma unroll
        for(int nt = 0; nt < 8; nt++)
          mma_bf16(acc[mt][nt], ahk[mt], &bhk[nt>>1][(nt&1)*2]);
      #pragma unroll
      for(int mt = 0; mt < 4; mt++)
        #pragma unroll
        for(int nt = 0; nt < 8; nt++)
          mma_bf16(acc[mt][nt], ahk[mt], &blk[nt>>1][(nt&1)*2]);
      #pragma unroll
      for(int mt = 0; mt < 4; mt++)
        #pragma unroll
        for(int nt = 0; nt < 8; nt++)
          mma_bf16(acc[mt][nt], alk[mt], &bhk[nt>>1][(nt&1)*2]);
    }
  }

  // ---- epilogue ----
  int mrow = lane >> 2;
  int ncol = (lane & 3) * 2;
  #pragma unroll
  for(int mt = 0; mt < 4; mt++){
    #pragma unroll
    for(int nt = 0; nt < 8; nt++){
      #pragma unroll
      for(int hf = 0; hf < 2; hf++){
        long gm = m0 + wm*64 + mt*16 + mrow + hf*8;
        int  gn = n0 + wn*64 + nt*8 + ncol;
        float v0 = acc[mt][nt][hf*2+0];
        float v1 = acc[mt][nt][hf*2+1];
        if(g.bias){ v0 += g.bias[gn]; v1 += g.bias[gn+1]; }
        if(ACT == 1){ v0 = fmaxf(v0,0.f); v1 = fmaxf(v1,0.f); }
        else if(ACT == 2){ v0 = sgm(v0); v1 = sgm(v1); }
        else if(ACT == 3){ v0 = fmaxf(v0,0.f); v0 *= v0; v1 = fmaxf(v1,0.f); v1 *= v1; }
        if(OUT == 0){
          float* cp = g.Co + gm*N + gn;
          if(EPI == 1){ v0 += cp[0]; v1 += cp[1]; }
          else if(EPI == 2){
            const float* mp = g.mul + gm*N + gn;
            v0 = cp[0] + mp[0]*v0; v1 = cp[1] + mp[1]*v1;
          }
          *(float2*)cp = make_float2(v0, v1);
        } else {
          uint32_t hh, ll;
          split2(v0, v1, hh, ll);
          *(uint32_t*)&g.Ch[gm*N + gn] = hh;
          *(uint32_t*)&g.Cl[gm*N + gn] = ll;
        }
      }
    }
  }
}

// ---------------- conv1: direct, split bf16 output ----------------------------
__global__ void conv1_k(const float* __restrict__ x, const float* __restrict__ w,
                        const float* __restrict__ bias){
  int t = blockIdx.x*256 + threadIdx.x;
  int co = t & 127;
  int rest = t >> 7;
  int wo = rest % W1; rest /= W1;
  int ho = rest % H1; int b = rest / H1;
  float acc = bias[co];
  int hi0 = 2*ho - 1, wi0 = 2*wo - 1;
  #pragma unroll
  for(int kh=0; kh<3; kh++){
    int hi = hi0 + kh;
    if(hi < 0 || hi >= LEN) continue;
    #pragma unroll
    for(int kw=0; kw<3; kw++){
      int wi = wi0 + kw;
      if(wi < 0 || wi >= FREQ) continue;
      acc = fmaf(x[(hi + (long)b*LEN)*FREQ + wi], w[co*9 + kh*3 + kw], acc);
    }
  }
  acc = fmaxf(acc, 0.f);
  bf h = __float2bfloat16(acc);
  g_c1h[t] = h;
  g_c1l[t] = __float2bfloat16(acc - __bfloat162float(h));
}

// ---------------- conv weight prep --------------------------------------------
__global__ void prep_conv_k(const float* __restrict__ w2, const float* __restrict__ w3){
  int t = blockIdx.x*256 + threadIdx.x;
  if(t < C2*K2C){
    int co = t / K2C; int idx = t % K2C;
    int r = idx / C1; int ci = idx % C1;
    float v = w2[co*(C1*9) + ci*9 + r];
    bf h = __float2bfloat16(v);
    g_w2Th[t] = h; g_w2Tl[t] = __float2bfloat16(v - __bfloat162float(h));
  } else {
    int u = t - C2*K2C;
    if(u >= C3*K3C) return;
    int co = u / K3C; int idx = u % K3C;
    int r = idx / C2; int ci = idx % C2;
    float v = w3[co*(C2*9) + ci*9 + r];
    bf h = __float2bfloat16(v);
    g_w3Th[u] = h; g_w3Tl[u] = __float2bfloat16(v - __bfloat162float(h));
  }
}

// ------ big weight prep: transpose [R][C]->[C][R] + split + concat ------------
// embed weight additionally gets its K-index permuted (k = c*20+w -> k' = w*512+c)
// so the embed GEMM can read conv3 output (layout [m][w*512+c]) directly.
__global__ void prep_big_k(const float* __restrict__ embed_w,
                           const float* __restrict__ awk, const float* __restrict__ awv,
                           const float* __restrict__ awr, const float* __restrict__ awo,
                           const float* __restrict__ fwr, const float* __restrict__ fwk,
                           const float* __restrict__ fwv){
  int t = blockIdx.x;
  const float* in; bf *oh, *ol; int R, C, tr, tc;
  bool permK = false;
  if(t < 5120){
    in = embed_w; oh = g_ewTh; ol = g_ewTl; R = KE; C = DIM;
    tr = t / 16; tc = t % 16;
    permK = true;
  } else {
    int u = t - 5120;
    int i = u / 3328; int v = u % 3328;
    long o2 = (long)i*DIM*DIM, oh2 = (long)i*DIM*HID;
    long qb = (long)i*3*DIM*DIM, fb = (long)i*(HID+DIM)*DIM;
    if(v < 768){
      int kind = v / 256; int vv = v % 256;
      R = DIM; C = DIM; tr = vv / 16; tc = vv % 16;
      in = (kind == 0 ? awk : kind == 1 ? awv : awr) + o2;
      oh = g_aqkvTh + qb + (long)kind*DIM*DIM;
      ol = g_aqkvTl + qb + (long)kind*DIM*DIM;
    } else if(v < 1024){
      int vv = v - 768;
      R = DIM; C = DIM; tr = vv / 16; tc = vv % 16;
      in = awo + o2; oh = g_awoTh + o2; ol = g_awoTl + o2;
    } else if(v < 2048){
      int vv = v - 1024;
      R = DIM; C = HID; tr = vv / 64; tc = vv % 64;
      in = fwk + oh2; oh = g_fkrTh + fb; ol = g_fkrTl + fb;
    } else if(v < 2304){
      int vv = v - 2048;
      R = DIM; C = DIM; tr = vv / 16; tc = vv % 16;
      in = fwr + o2;
      oh = g_fkrTh + fb + (long)HID*DIM;
      ol = g_fkrTl + fb + (long)HID*DIM;
    } else {
      int vv = v - 2304;
      R = HID; C = DIM; tr = vv / 16; tc = vv % 16;
      in = fwv + oh2; oh = g_fwvTh + oh2; ol = g_fwvTl + oh2;
    }
  }
  __shared__ float tile[32][33];
  int r0 = tr*32, c0 = tc*32;
  int x = c0 + threadIdx.x;
  for(int dy = threadIdx.y; dy < 32; dy += 8)
    tile[dy][threadIdx.x] = in[(long)(r0 + dy)*C + x];
  __syncthreads();
  int xo = r0 + threadIdx.x;
  for(int dy = threadIdx.y; dy < 32; dy += 8){
    float v = tile[threadIdx.x][dy];
    bf h = __float2bfloat16(v);
    long kk = xo;
    if(permK){ int cc = xo / W2, ww = xo % W2; kk = (long)ww*512 + cc; }
    long oidx = (long)(c0 + dy)*R + kk;
    oh[oidx] = h; ol[oidx] = __float2bfloat16(v - __bfloat162float(h));
  }
}

// ---------------- LayerNorm -----------------------------------------------------
__global__ void ln_k(const float* __restrict__ x, const float* __restrict__ gw,
                     const float* __restrict__ gb, float* __restrict__ o){
  int m = blockIdx.x;
  int tid = threadIdx.x;
  const float* xr = x + (long)m*DIM;
  float v[4]; float s = 0.f, sq = 0.f;
  #pragma unroll
  for(int j=0;j<4;j++){ float t = xr[tid + j*128]; v[j] = t; s += t; sq += t*t; }
  #pragma unroll
  for(int off=16; off; off>>=1){
    s  += __shfl_xor_sync(0xffffffffu, s,  off);
    sq += __shfl_xor_sync(0xffffffffu, sq, off);
  }
  __shared__ float ss[4], sqs[4];
  if((tid & 31) == 0){ ss[tid>>5] = s; sqs[tid>>5] = sq; }
  __syncthreads();
  s  = (ss[0]+ss[1]) + (ss[2]+ss[3]);
  sq = (sqs[0]+sqs[1]) + (sqs[2]+sqs[3]);
  float mean = s * (1.f/DIM);
  float var  = sq * (1.f/DIM) - mean*mean;
  float rstd = rsqrtf(var + 1e-5f);
  float* orow = o + (long)m*DIM;
  #pragma unroll
  for(int j=0;j<4;j++){
    int d = tid + j*128;
    orow[d] = (v[j] - mean)*rstd*gw[d] + gb[d];
  }
}

// ---------------- time-shift mixes ----------------------------------------------
__global__ void mix3_k(const float* __restrict__ xn, const float* __restrict__ mk,
                       const float* __restrict__ mv, const float* __restrict__ mr){
  int g = blockIdx.x*256 + threadIdx.x;
  int t = g*2;
  int d = t & (DIM-1);
  int tok = (t >> 9) & (USEQ-1);
  float2 cur = *(const float2*)&xn[t];
  float2 sh = tok ? *(const float2*)&xn[t - DIM] : make_float2(0.f, 0.f);
  float d0 = cur.x - sh.x, d1 = cur.y - sh.y;
  uint32_t h, l;
  split2(fmaf(d0, mk[d], sh.x), fmaf(d1, mk[d+1], sh.y), h, l);
  *(uint32_t*)&g_xkh[t] = h; *(uint32_t*)&g_xkl[t] = l;
  split2(fmaf(d0, mv[d], sh.x), fmaf(d1, mv[d+1], sh.y), h, l);
  *(uint32_t*)&g_xvh[t] = h; *(uint32_t*)&g_xvl[t] = l;
  split2(fmaf(d0, mr[d], sh.x), fmaf(d1, mr[d+1], sh.y), h, l);
  *(uint32_t*)&g_xrh[t] = h; *(uint32_t*)&g_xrl[t] = l;
}
__global__ void mix2_k(const float* __restrict__ xn, const float* __restrict__ mk,
                       const float* __restrict__ mr){
  int g = blockIdx.x*256 + threadIdx.x;
  int t = g*2;
  int d = t & (DIM-1);
  int tok = (t >> 9) & (USEQ-1);
  float2 cur = *(const float2*)&xn[t];
  float2 sh = tok ? *(const float2*)&xn[t - DIM] : make_float2(0.f, 0.f);
  float d0 = cur.x - sh.x, d1 = cur.y - sh.y;
  uint32_t h, l;
  split2(fmaf(d0, mk[d], sh.x), fmaf(d1, mk[d+1], sh.y), h, l);
  *(uint32_t*)&g_xkh[t] = h; *(uint32_t*)&g_xkl[t] = l;
  split2(fmaf(d0, mr[d], sh.x), fmaf(d1, mr[d+1], sh.y), h, l);
  *(uint32_t*)&g_xrh[t] = h; *(uint32_t*)&g_xrl[t] = l;
}

// ---------------- WKV scan, pipelined, bf16 split output ------------------------
#define WG 8
__device__ __forceinline__ void wkv_load(const float* kp, const float* vp,
                                         const float* rp, long off0,
                                         float* kb, float* vb, float* rb){
  #pragma unroll
  for(int j=0;j<WG;j++){
    long off = off0 + (long)j*DIM;
    kb[j] = __ldg(kp + off); vb[j] = __ldg(vp + off); rb[j] = __ldg(rp + off);
  }
}
__device__ __forceinline__ void wkv_step(float* kb, float* vb, float* rb,
                                         bf* oh, bf* ol, long off0,
                                         float w, float u,
                                         float& aa, float& bb, float& pp){
  #pragma unroll
  for(int j=0;j<WG;j++){
    float kt = kb[j], vt = vb[j];
    float ww = u + kt;
    float p  = fmaxf(pp, ww);
    float e1 = __expf(pp - p), e2 = __expf(ww - p);
    float o  = rb[j] * (e1*aa + e2*vt) / (e1*bb + e2);
    bf h = __float2bfloat16(o);
    long off = off0 + (long)j*DIM;
    oh[off] = h;
    ol[off] = __float2bfloat16(o - __bfloat162float(h));
    float ww2 = pp + w;
    float p2  = fmaxf(ww2, kt);
    e1 = __expf(ww2 - p2); e2 = __expf(kt - p2);
    aa = e1*aa + e2*vt; bb = e1*bb + e2; pp = p2;
  }
}
__global__ void wkv_k(const float* __restrict__ k, const float* __restrict__ v,
                      const float* __restrict__ r,
                      const float* __restrict__ dec, const float* __restrict__ fir){
  int t = blockIdx.x*blockDim.x + threadIdx.x;
  int d = t & (DIM-1); int b = t >> 9;
  float w = -__expf(dec[d]);
  float u = fir[d];
  float aa = 0.f, bb = 0.f, pp = -1e38f;
  long base = (long)b*USEQ*DIM + d;
  const float* kp = k + base;
  const float* vp = v + base;
  const float* rp = r + base;
  bf* oh = g_rwh + base;
  bf* ol = g_rwl + base;
  const int NG = USEQ/WG;
  float k0b[WG], v0b[WG], r0b[WG];
  float k1b[WG], v1b[WG], r1b[WG];
  wkv_load(kp, vp, rp, 0, k0b, v0b, r0b);
  for(int g=0; g<NG; g+=2){
    long off1 = (long)(g+1)*WG*DIM;
    wkv_load(kp, vp, rp, off1, k1b, v1b, r1b);
    wkv_step(k0b, v0b, r0b, oh, ol, (long)g*WG*DIM, w, u, aa, bb, pp);
    if(g+2 < NG){
      long off2 = (long)(g+2)*WG*DIM;
      wkv_load(kp, vp, rp, off2, k0b, v0b, r0b);
    }
    wkv_step(k1b, v1b, r1b, oh, ol, off1, w, u, aa, bb, pp);
  }
}

// ---------------- olens tail -----------------------------------------------------
__global__ void tail_k(const int* __restrict__ x_len, float* __restrict__ out, int out_size){
  int b = threadIdx.x;
  if(b < BATCH && out_size >= HTOK + BATCH){
    int l1 = (x_len[b] - 1)/2 + 1;
    int ol = (l1 - 1)/2 + 1;
    out[HTOK + b] = (float)ol;
  }
}

// ---------------- host side ------------------------------------------------------
template <typename T>
static void* symaddr(const T& s){ void* p = nullptr; cudaGetSymbolAddress(&p, s); return p; }

template<int ACT, int EPI, int OUT, int IMC>
static void gemm(int M, int N, int K, const GP& g){
  cudaFuncSetAttribute(mgemm_k<ACT,EPI,OUT,IMC>, cudaFuncAttributeMaxDynamicSharedMemorySize, MSMEM);
  dim3 grid(N/256, M/128);
  mgemm_k<ACT,EPI,OUT,IMC><<<grid, 256, MSMEM>>>(M, N, K, g);
}

extern "C" void kernel_launch(void* const* d_in, const int* in_sizes, int n_in,
                              void* d_out, int out_size){
  const float* x       = (const float*)d_in[0];
  const int*   x_len   = (const int*)  d_in[1];
  const float* conv1_w = (const float*)d_in[2];
  const float* conv1_b = (const float*)d_in[3];
  const float* conv2_w = (const float*)d_in[4];
  const float* conv2_b = (const float*)d_in[5];
  const float* conv3_w = (const float*)d_in[6];
  const float* conv3_b = (const float*)d_in[7];
  const float* embed_w = (const float*)d_in[8];
  const float* embed_b = (const float*)d_in[9];
  const float* eln_g   = (const float*)d_in[10];
  const float* eln_b   = (const float*)d_in[11];
  const float* lag     = (const float*)d_in[12];
  const float* lab     = (const float*)d_in[13];
  const float* dec     = (const float*)d_in[14];
  const float* fir     = (const float*)d_in[15];
  const float* amk     = (const float*)d_in[16];
  const float* amv     = (const float*)d_in[17];
  const float* amr     = (const float*)d_in[18];
  const float* awk     = (const float*)d_in[19];
  const float* awv     = (const float*)d_in[20];
  const float* awr     = (const float*)d_in[21];
  const float* awo     = (const float*)d_in[22];
  const float* lfg     = (const float*)d_in[23];
  const float* lfb     = (const float*)d_in[24];
  const float* fmk     = (const float*)d_in[25];
  const float* fmr     = (const float*)d_in[26];
  const float* fwk     = (const float*)d_in[27];
  const float* fwv     = (const float*)d_in[28];
  const float* fwr     = (const float*)d_in[29];
  const float* flg     = (const float*)d_in[30];
  const float* flb     = (const float*)d_in[31];
  float* out = (float*)d_out;

  bf* p_c1h = (bf*)symaddr(g_c1h); bf* p_c1l = (bf*)symaddr(g_c1l);
  bf* p_c2h = (bf*)symaddr(g_c2h); bf* p_c2l = (bf*)symaddr(g_c2l);
  bf* p_c3h = (bf*)symaddr(g_c3h); bf* p_c3l = (bf*)symaddr(g_c3l);
  float* p_t0 = (float*)symaddr(g_t0);
  float* p_h  = (float*)symaddr(g_h);
  float* p_xn = (float*)symaddr(g_xn);
  bf* p_xkh = (bf*)symaddr(g_xkh); bf* p_xkl = (bf*)symaddr(g_xkl);
  bf* p_xvh = (bf*)symaddr(g_xvh); bf* p_xvl = (bf*)symaddr(g_xvl);
  bf* p_xrh = (bf*)symaddr(g_xrh); bf* p_xrl = (bf*)symaddr(g_xrl);
  float* p_k = (float*)symaddr(g_k);
  float* p_v = (float*)symaddr(g_v);
  float* p_r = (float*)symaddr(g_r);
  bf* p_rwh = (bf*)symaddr(g_rwh); bf* p_rwl = (bf*)symaddr(g_rwl);
  bf* p_kkh = (bf*)symaddr(g_kkh); bf* p_kkl = (bf*)symaddr(g_kkl);
  bf* p_w2Th = (bf*)symaddr(g_w2Th); bf* p_w2Tl = (bf*)symaddr(g_w2Tl);
  bf* p_w3Th = (bf*)symaddr(g_w3Th); bf* p_w3Tl = (bf*)symaddr(g_w3Tl);
  bf* p_ewTh = (bf*)symaddr(g_ewTh); bf* p_ewTl = (bf*)symaddr(g_ewTl);
  bf* p_aqkvTh = (bf*)symaddr(g_aqkvTh); bf* p_aqkvTl = (bf*)symaddr(g_aqkvTl);
  bf* p_awoTh  = (bf*)symaddr(g_awoTh);  bf* p_awoTl  = (bf*)symaddr(g_awoTl);
  bf* p_fkrTh  = (bf*)symaddr(g_fkrTh);  bf* p_fkrTl  = (bf*)symaddr(g_fkrTl);
  bf* p_fwvTh  = (bf*)symaddr(g_fwvTh);  bf* p_fwvTl  = (bf*)symaddr(g_fwvTl);

  // launches 1-6 (launch 6 = embed GEMM K=10240, profiled by ncu -s 5 -c 1)
  prep_conv_k<<<(C2*K2C + C3*K3C + 255)/256, 256>>>(conv2_w, conv3_w);
  conv1_k<<<(BATCH*H1*W1*C1)/256, 256>>>(x, conv1_w, conv1_b);
  prep_big_k<<<18432, dim3(32,8)>>>(embed_w, awk, awv, awr, awo, fwr, fwk, fwv);
  { GP g = gp0(); g.Ah = p_c1h; g.Al = p_c1l; g.Bh = p_w2Th; g.Bl = p_w2Tl;
    g.bias = conv2_b; g.Ch = p_c2h; g.Cl = p_c2l;
    gemm<1,0,1,1>(MCONV, C2, K2C, g); }
  { GP g = gp0(); g.Ah = p_c2h; g.Al = p_c2l; g.Bh = p_w3Th; g.Bl = p_w3Tl;
    g.bias = conv3_b; g.Ch = p_c3h; g.Cl = p_c3l;
    gemm<1,0,1,2>(MCONV, C3, K3C, g); }
  // embed GEMM reads c3 directly (weight K-index pre-permuted in prep_big_k)
  { GP g = gp0(); g.Ah = p_c3h; g.Al = p_c3l; g.Bh = p_ewTh; g.Bl = p_ewTl;
    g.bias = embed_b; g.Co = p_t0;
    gemm<0,0,0,0>(MT, DIM, KE, g); }
  ln_k<<<MT, 128>>>(p_t0, eln_g, eln_b, p_h);

  // ---- RWKV blocks ----
  for(int i = 0; i < NB_; i++){
    long w2 = (long)i*DIM*DIM;
    long wh = (long)i*DIM*HID;
    long qb = (long)i*3*DIM*DIM;
    long fb = (long)i*(HID+DIM)*DIM;
    // time mixing
    ln_k<<<MT, 128>>>(p_h, lag + i*DIM, lab + i*DIM, p_xn);
    mix3_k<<<HTOK/512, 256>>>(p_xn, amk + i*DIM, amv + i*DIM, amr + i*DIM);
    { GP g = gp0(); g.Ah = p_xkh; g.Al = p_xkl;
      g.Bh = p_aqkvTh + qb; g.Bl = p_aqkvTl + qb; g.Co = p_k;
      gemm<0,0,0,0>(MT, DIM, DIM, g); }
    { GP g = gp0(); g.Ah = p_xvh; g.Al = p_xvl;
      g.Bh = p_aqkvTh + qb + (long)DIM*DIM; g.Bl = p_aqkvTl + qb + (long)DIM*DIM; g.Co = p_v;
      gemm<0,0,0,0>(MT, DIM, DIM, g); }
    { GP g = gp0(); g.Ah = p_xrh; g.Al = p_xrl;
      g.Bh = p_aqkvTh + qb + 2L*DIM*DIM; g.Bl = p_aqkvTl + qb + 2L*DIM*DIM; g.Co = p_r;
      gemm<2,0,0,0>(MT, DIM, DIM, g); }
    wkv_k<<<(BATCH*DIM)/32, 32>>>(p_k, p_v, p_r, dec + i*DIM, fir + i*DIM);
    { GP g = gp0(); g.Ah = p_rwh; g.Al = p_rwl;
      g.Bh = p_awoTh + w2; g.Bl = p_awoTl + w2; g.Co = p_h;
      gemm<0,1,0,0>(MT, DIM, DIM, g); }
    // channel mixing
    ln_k<<<MT, 128>>>(p_h, lfg + i*DIM, lfb + i*DIM, p_xn);
    mix2_k<<<HTOK/512, 256>>>(p_xn, fmk + i*DIM, fmr + i*DIM);
    { GP g = gp0(); g.Ah = p_xkh; g.Al = p_xkl;
      g.Bh = p_fkrTh + fb; g.Bl = p_fkrTl + fb; g.Ch = p_kkh; g.Cl = p_kkl;
      gemm<3,0,1,0>(MT, HID, DIM, g); }
    { GP g = gp0(); g.Ah = p_xrh; g.Al = p_xrl;
      g.Bh = p_fkrTh + fb + (long)HID*DIM; g.Bl = p_fkrTl + fb + (long)HID*DIM; g.Co = p_r;
      gemm<2,0,0,0>(MT, DIM, DIM, g); }
    { GP g = gp0(); g.Ah = p_kkh; g.Al = p_kkl;
      g.Bh = p_fwvTh + wh; g.Bl = p_fwvTl + wh; g.Co = p_h; g.mul = p_r;
      gemm<0,2,0,0>(MT, DIM, HID, g); }
  }

  ln_k<<<MT, 128>>>(p_h, flg, flb, out);
  tail_k<<<1, 32>>>(x_len, out, out_size);
}